// round 10
// baseline (speedup 1.0000x reference)
#include <cuda_runtime.h>

// LSTM char-RNN, fully fused single persistent kernel — R10: deep pipeline.
//   inputs [1024,256] i32, kernel Wx [128,1024] f32, recurrent R [256,1024] f32,
//   bias [1024] f32, dense_w [256,128] f32, dense_b [128] f32
//   out = softmax(h_T @ dense_w + dense_b)  -> [1024,128] f32
//
// Grid: 128 CTAs x 256 threads. CTA owns 8 batch rows; thread owns 1 unit
// (4 gates x 8 rows = 32 fp32 accumulators as 16 f32x2). h in SMEM, c in regs.
// K-loop: chunks of 8 k, double-buffered with one-chunk (~256 issue-cyc) lead
// >= L2 hit latency; prefetch wraps across the step boundary (R addresses are
// step-invariant), so steady-state R loads are fully hidden. Wx gather issued
// mid-loop, consumed in the epilogue. All step indices preloaded to SMEM.

#define BATCHN   1024
#define SEQLEN   256
#define UNITSN   256
#define NCHARS   128
#define BT       8
#define NCTA     (BATCHN / BT)   // 128
#define NTHR     256
#define FOURU    (4 * UNITSN)    // 1024
#define KCH      8               // k per chunk
#define NCHUNK   (UNITSN / KCH)  // 32

#define FMA2(acc, a, b) \
    asm("fma.rn.f32x2 %0, %1, %2, %0;" : "+l"(acc) : "l"(a), "l"(b))

__device__ __forceinline__ unsigned long long bcast2(float v) {
    unsigned long long r;
    unsigned u = __float_as_uint(v);
    asm("mov.b64 %0, {%1, %1};" : "=l"(r) : "r"(u));
    return r;
}

__device__ __forceinline__ void unpack2(unsigned long long v, float& lo, float& hi) {
    unsigned a, b;
    asm("mov.b64 {%0, %1}, %2;" : "=r"(a), "=r"(b) : "l"(v));
    lo = __uint_as_float(a);
    hi = __uint_as_float(b);
}

// exp-based activations: ~1e-6 rel error, survives the recurrence (tanh.approx
// at ~1e-3 would not survive the 1e-3 output threshold).
__device__ __forceinline__ float fast_sigmoid(float x) {
    return __fdividef(1.0f, 1.0f + __expf(-x));
}
__device__ __forceinline__ float fast_tanh(float x) {
    float e = __expf(2.0f * x);            // inf for large x -> result 1, ok
    return 1.0f - __fdividef(2.0f, e + 1.0f);
}

// Stage 32 R values (8 k x 4 gates) for one chunk into registers.
__device__ __forceinline__ void load_chunk8(
    float (&buf)[32], const float* __restrict__ Rbase, int kc)
{
    const float* p = Rbase + kc * (KCH * FOURU);
#pragma unroll
    for (int kk = 0; kk < KCH; ++kk)
#pragma unroll
        for (int g = 0; g < 4; ++g)
            buf[kk * 4 + g] = p[kk * FOURU + g * UNITSN];
}

// 8 k-values of the recurrent GEMM.
// acc2[g][p] += h[k][2p..2p+1] * R[k][g*U+tid]; h pairs via 128-bit broadcast LDS.
__device__ __forceinline__ void compute_chunk8(
    unsigned long long (&acc2)[4][BT / 2],
    const float (&buf)[32],
    const float (*h_s)[BT],
    int k0)
{
#pragma unroll
    for (int kk = 0; kk < KCH; ++kk) {
        const ulonglong2* hp = (const ulonglong2*)(&h_s[k0 + kk][0]);
        ulonglong2 pA = hp[0], pB = hp[1];
#pragma unroll
        for (int g = 0; g < 4; ++g) {
            unsigned long long rv = bcast2(buf[kk * 4 + g]);
            FMA2(acc2[g][0], pA.x, rv);
            FMA2(acc2[g][1], pA.y, rv);
            FMA2(acc2[g][2], pB.x, rv);
            FMA2(acc2[g][3], pB.y, rv);
        }
    }
}

__global__ void __launch_bounds__(NTHR, 1) lstm_fused_kernel(
    const int*   __restrict__ inp,
    const float* __restrict__ Wx,
    const float* __restrict__ R,
    const float* __restrict__ bias,
    const float* __restrict__ Wd,
    const float* __restrict__ bd,
    float*       __restrict__ out)
{
    __shared__ __align__(16) float h_s[UNITSN][BT];   // [unit][row], 8 KB
    __shared__ int idx_all[SEQLEN][BT];               // all step indices, 8 KB

    const int tid = threadIdx.x;          // unit index 0..255
    const int b0  = blockIdx.x * BT;      // first batch row of this CTA

    // Preload all indices for this CTA's 8 rows (coalesced over t).
    for (int i = tid; i < SEQLEN * BT; i += NTHR) {
        int r = i >> 8;          // 0..7
        int t = i & (SEQLEN - 1);
        idx_all[t][r] = inp[(b0 + r) * SEQLEN + t];
    }
    // h0 = 0
    for (int i = tid; i < UNITSN * BT; i += NTHR)
        ((float*)h_s)[i] = 0.0f;

    float c_reg[BT];
#pragma unroll
    for (int r = 0; r < BT; ++r) c_reg[r] = 0.0f;

    unsigned long long bia2[4];
#pragma unroll
    for (int g = 0; g < 4; ++g) bia2[g] = bcast2(bias[g * UNITSN + tid]);

    const float* Rbase = R + tid;   // column base; +g*UNITSN per gate

    // Prime the pipeline: chunks 0,1 (addresses are step-invariant).
    float ra[32], rb[32];
    load_chunk8(ra, Rbase, 0);
    load_chunk8(rb, Rbase, 1);

    for (int t = 0; t < SEQLEN; ++t) {
        __syncthreads();   // h_s writes from step t-1 visible

        // acc = bias (x_proj added in epilogue)
        unsigned long long acc2[4][BT / 2];
#pragma unroll
        for (int g = 0; g < 4; ++g)
#pragma unroll
            for (int p = 0; p < BT / 2; ++p)
                acc2[g][p] = bia2[g];

        // ---- K loop part 1: chunks 0..23, rotate with 1-chunk (~256cyc) lead ----
        for (int kc = 0; kc < 24; kc += 2) {
            compute_chunk8(acc2, ra, h_s, kc * KCH);
            load_chunk8(ra, Rbase, (kc + 2) & (NCHUNK - 1));
            compute_chunk8(acc2, rb, h_s, (kc + 1) * KCH);
            load_chunk8(rb, Rbase, (kc + 3) & (NCHUNK - 1));
        }

        // ---- Wx gather for this step (consumed ~2k cyc later in epilogue) ----
        float xf[4][BT];
#pragma unroll
        for (int r = 0; r < BT; ++r) {
            const float* wrow = Wx + idx_all[t][r] * FOURU + tid;
#pragma unroll
            for (int g = 0; g < 4; ++g)
                xf[g][r] = wrow[g * UNITSN];
        }

        // ---- K loop part 2: chunks 24..31; wrap prefetch loads chunks 0,1
        //      for step t+1 before the barriers (fully hidden) ----
        for (int kc = 24; kc < NCHUNK; kc += 2) {
            compute_chunk8(acc2, ra, h_s, kc * KCH);
            load_chunk8(ra, Rbase, (kc + 2) & (NCHUNK - 1));
            compute_chunk8(acc2, rb, h_s, (kc + 1) * KCH);
            load_chunk8(rb, Rbase, (kc + 3) & (NCHUNK - 1));
        }

        // ---- gates + state update (registers only) ----
        float hv[BT];
#pragma unroll
        for (int p = 0; p < BT / 2; ++p) {
            float zi0, zi1, zf0, zf1, zg0, zg1, zo0, zo1;
            unpack2(acc2[0][p], zi0, zi1);
            unpack2(acc2[1][p], zf0, zf1);
            unpack2(acc2[2][p], zg0, zg1);
            unpack2(acc2[3][p], zo0, zo1);
            zi0 += xf[0][2 * p]; zi1 += xf[0][2 * p + 1];
            zf0 += xf[1][2 * p]; zf1 += xf[1][2 * p + 1];
            zg0 += xf[2][2 * p]; zg1 += xf[2][2 * p + 1];
            zo0 += xf[3][2 * p]; zo1 += xf[3][2 * p + 1];
            {
                float i = fast_sigmoid(zi0), f = fast_sigmoid(zf0);
                float g = fast_tanh(zg0),    o = fast_sigmoid(zo0);
                float c = f * c_reg[2 * p] + i * g;
                c_reg[2 * p] = c;
                hv[2 * p] = o * fast_tanh(c);
            }
            {
                float i = fast_sigmoid(zi1), f = fast_sigmoid(zf1);
                float g = fast_tanh(zg1),    o = fast_sigmoid(zo1);
                float c = f * c_reg[2 * p + 1] + i * g;
                c_reg[2 * p + 1] = c;
                hv[2 * p + 1] = o * fast_tanh(c);
            }
        }

        __syncthreads();   // all readers done with h_s for this step
        *(float4*)(&h_s[tid][0]) = make_float4(hv[0], hv[1], hv[2], hv[3]);
        *(float4*)(&h_s[tid][4]) = make_float4(hv[4], hv[5], hv[6], hv[7]);
    }
    __syncthreads();       // final h visible to all warps

    // ---- dense + softmax: warp w handles batch row b0+w, lane handles 4 cols ----
    const int w = tid >> 5;
    const int l = tid & 31;

    float4 bb = ((const float4*)bd)[l];
    float a0 = bb.x, a1 = bb.y, a2 = bb.z, a3 = bb.w;
#pragma unroll 4
    for (int u = 0; u < UNITSN; ++u) {
        float hvv = h_s[u][w];                                  // warp broadcast
        float4 wv = *(const float4*)(Wd + u * NCHARS + 4 * l);  // coalesced
        a0 += hvv * wv.x; a1 += hvv * wv.y;
        a2 += hvv * wv.z; a3 += hvv * wv.w;
    }
    float m = fmaxf(fmaxf(a0, a1), fmaxf(a2, a3));
#pragma unroll
    for (int off = 16; off; off >>= 1)
        m = fmaxf(m, __shfl_xor_sync(0xffffffffu, m, off));
    float e0 = __expf(a0 - m), e1 = __expf(a1 - m);
    float e2 = __expf(a2 - m), e3 = __expf(a3 - m);
    float s = e0 + e1 + e2 + e3;
#pragma unroll
    for (int off = 16; off; off >>= 1)
        s += __shfl_xor_sync(0xffffffffu, s, off);
    float inv = 1.0f / s;
    *(float4*)(out + (b0 + w) * NCHARS + 4 * l) =
        make_float4(e0 * inv, e1 * inv, e2 * inv, e3 * inv);
}

extern "C" void kernel_launch(void* const* d_in, const int* in_sizes, int n_in,
                              void* d_out, int out_size)
{
    const int*   inp  = (const int*)d_in[0];    // [1024, 256]
    const float* Wx   = (const float*)d_in[1];  // [128, 1024]
    const float* R    = (const float*)d_in[2];  // [256, 1024]
    const float* bias = (const float*)d_in[3];  // [1024]
    const float* Wd   = (const float*)d_in[4];  // [256, 128]
    const float* bd   = (const float*)d_in[5];  // [128]
    float*       out  = (float*)d_out;          // [1024, 128]

    lstm_fused_kernel<<<NCTA, NTHR>>>(inp, Wx, R, bias, Wd, bd, out);
}